// round 4
// baseline (speedup 1.0000x reference)
#include <cuda_runtime.h>
#include <math.h>

// Problem constants
#define Bn   128
#define Dn   256
#define Sn   512
#define Kn   50
#define Hn   256
#define NC   2
#define THRES 0.3f
#define TS   64
#define BS   (Bn*Sn)          // 65536

// Output layout (float32, concatenated tuple):
//  [0..255]       pred [B,NC]
//  [256]          0.0
//  [257]          concept_sim
//  [258]          concept_far
//  [259..+B*S*K)  topic_prob_nn [B,S,K]
//  [3277059]      ae_loss
#define OUT_NN   259
#define OUT_AE   (259 + Bn*Sn*Kn)   // 3277059

// ---------------- device scratch (no allocations allowed) ----------------
__device__ float g_tvnT[Kn*Dn];     // normalized topic vectors, [K][D]
__device__ float g_tpn[(size_t)Kn*BS]; // topic_prob_n, [K][B*S]  (13.1 MB)
__device__ float g_acc1[Bn*Hn];     // sum over s of rec1
__device__ float g_ae;
__device__ float g_sim;

// ---------------- init ----------------
__global__ void k_init() {
    int i = blockIdx.x*blockDim.x + threadIdx.x;
    if (i < Bn*Hn) g_acc1[i] = 0.f;
    if (i == 0) { g_ae = 0.f; g_sim = 0.f; }
}

// ---------------- tv normalization: tvnT[k][d] = tv[d][k]/max(||tv[:,k]||,1e-12) ----
__global__ void k_prep(const float* __restrict__ tv) {
    __shared__ float sred[256];
    int k = blockIdx.x, d = threadIdx.x;
    float v = tv[d*Kn + k];
    sred[d] = v*v;
    __syncthreads();
    for (int off = 128; off > 0; off >>= 1) {
        if (d < off) sred[d] += sred[d+off];
        __syncthreads();
    }
    float nrm = sqrtf(sred[0]);
    g_tvnT[k*Dn + d] = v / fmaxf(nrm, 1e-12f);
}

// ---------------- concept_far = (||sum_k tvn_k||^2 - K) / K^2 ----------------
__global__ void k_far(float* __restrict__ out) {
    __shared__ float sred[256];
    int d = threadIdx.x;
    float u = 0.f;
    for (int k = 0; k < Kn; k++) u += g_tvnT[k*Dn + d];
    sred[d] = u*u;
    __syncthreads();
    for (int off = 128; off > 0; off >>= 1) {
        if (d < off) sred[d] += sred[d+off];
        __syncthreads();
    }
    if (d == 0) out[258] = (sred[0] - (float)Kn) / (float)(Kn*Kn);
}

// ---------------- main fused kernel ----------------
// grid (8, 128): blockIdx.y = b, blockIdx.x = s-tile of 64. 256 threads.
// smem (floats): xs[64][257] | tp[64][51] | r1[64][257] | rn[64] | red[256]
#define SM_XS   0
#define SM_TP   16448
#define SM_R1   19712
#define SM_RN   36160
#define SM_RED  36224
#define SM_TOT  36480     // floats -> 145920 bytes

extern "C" __global__ void __launch_bounds__(256, 1)
k_main(const float* __restrict__ f, const float* __restrict__ rv1,
       const float* __restrict__ rv2, float* __restrict__ out)
{
    extern __shared__ float sm[];
    float* xs  = sm + SM_XS;
    float* tp  = sm + SM_TP;
    float* r1  = sm + SM_R1;
    float* rn  = sm + SM_RN;
    float* red = sm + SM_RED;

    const int tid = threadIdx.x;
    const int b = blockIdx.y;
    const int s0 = blockIdx.x * TS;

    // Phase 1: coalesced load of x tile [TS s][D d] (f is [B,D,S])
    const float* fb = f + (size_t)b*Dn*Sn + s0;
    for (int i = tid; i < Dn*TS; i += 256) {
        int d = i >> 6, sl = i & 63;
        xs[sl*257 + d] = fb[(size_t)d*Sn + sl];
    }
    __syncthreads();

    // Phase 2: per-s inverse norms
    {
        int s = tid & 63, part = tid >> 6;
        float a = 0.f;
        int d0 = part*64;
        #pragma unroll 8
        for (int d = d0; d < d0+64; d++) { float v = xs[s*257+d]; a += v*v; }
        red[part*64 + s] = a;
    }
    __syncthreads();
    if (tid < 64) {
        float nsq = red[tid] + red[64+tid] + red[128+tid] + red[192+tid];
        rn[tid] = 1.0f / fmaxf(sqrtf(nsq), 1e-12f);
    }
    __syncthreads();

    // Phase 3: topic_prob[s][k] = x . tvn_k   (register-blocked over k)
    {
        int s = tid & 63, kg = tid >> 6;
        float acc[13];
        #pragma unroll
        for (int j = 0; j < 13; j++) acc[j] = 0.f;
        for (int d = 0; d < Dn; d += 4) {
            float x0 = xs[s*257+d+0], x1 = xs[s*257+d+1];
            float x2 = xs[s*257+d+2], x3 = xs[s*257+d+3];
            #pragma unroll
            for (int j = 0; j < 13; j++) {
                int k = kg + 4*j;
                if (k < Kn) {
                    const float4 w = *reinterpret_cast<const float4*>(&g_tvnT[k*Dn + d]);
                    acc[j] += x0*w.x + x1*w.y + x2*w.z + x3*w.w;
                }
            }
        }
        #pragma unroll
        for (int j = 0; j < 13; j++) {
            int k = kg + 4*j;
            if (k < Kn) tp[s*51 + k] = acc[j];
        }
    }
    __syncthreads();

    // Phase 4: topic_prob_n -> scratch; threshold mask; normalized nn (in tp)
    if (tid < 64) {
        int s = tid;
        float rns = rn[s];
        int bs = b*Sn + s0 + s;
        float sum = 0.f;
        for (int k = 0; k < Kn; k++) {
            float t  = tp[s*51+k];
            float tn = t * rns;
            g_tpn[(size_t)k*BS + bs] = tn;
            float am = (tn > THRES) ? t : 0.f;
            tp[s*51+k] = am;
            sum += am;
        }
        float inv = 1.0f / (sum + 0.001f + 1e-8f);
        for (int k = 0; k < Kn; k++) tp[s*51+k] *= inv;
    }
    __syncthreads();

    // write topic_prob_nn tile to output (contiguous, coalesced)
    {
        float* onn = out + OUT_NN + (size_t)(b*Sn + s0) * Kn;
        for (int i = tid; i < TS*Kn; i += 256) {
            int s = i / Kn, k = i - s*Kn;
            onn[i] = tp[s*51 + k];
        }
    }

    // Phase 5: rec1[s][h] = relu(nn . rv1[:,h])
    {
        int s = tid & 63, hg = tid >> 6;
        for (int jj = 0; jj < 16; jj++) {
            int h = 4*hg + 16*jj;
            float a0=0.f, a1=0.f, a2=0.f, a3=0.f;
            for (int k = 0; k < Kn; k++) {
                float a = tp[s*51+k];
                const float4 w = *reinterpret_cast<const float4*>(&rv1[k*Hn + h]);
                a0 += a*w.x; a1 += a*w.y; a2 += a*w.z; a3 += a*w.w;
            }
            r1[s*257+h+0] = fmaxf(a0, 0.f);
            r1[s*257+h+1] = fmaxf(a1, 0.f);
            r1[s*257+h+2] = fmaxf(a2, 0.f);
            r1[s*257+h+3] = fmaxf(a3, 0.f);
        }
    }
    __syncthreads();

    // Phase 5b: accumulate sum over s of rec1 (for pred = mean_s rec1 @ rv2 @ Wc)
    {
        float a = 0.f;
        #pragma unroll 8
        for (int s = 0; s < TS; s++) a += r1[s*257 + tid];
        atomicAdd(&g_acc1[b*Hn + tid], a);
    }

    // Phase 6: rec2 on the fly (packed f32x2 FMA) + ae accumulation.
    // warp g owns d in [g*32, g*32+32); lane handles s=lane and s=lane+32.
    float aeacc = 0.f;
    {
        int lane = tid & 31, g = tid >> 5;
        int sA = lane, sB = lane + 32;
        float rnA = rn[sA], rnB = rn[sB];
        for (int p = 0; p < 2; p++) {
            int dbase = g*32 + p*16;
            unsigned long long accA[4][2], accB[4][2];
            #pragma unroll
            for (int q = 0; q < 4; q++) {
                accA[q][0]=0ull; accA[q][1]=0ull; accB[q][0]=0ull; accB[q][1]=0ull;
            }
            #pragma unroll 2
            for (int h = 0; h < Hn; h++) {
                float a0 = r1[sA*257+h];
                float a1 = r1[sB*257+h];
                unsigned long long a0p, a1p;
                asm("mov.b64 %0, {%1, %1};" : "=l"(a0p) : "f"(a0));
                asm("mov.b64 %0, {%1, %1};" : "=l"(a1p) : "f"(a1));
                const ulonglong2* wp =
                    reinterpret_cast<const ulonglong2*>(&rv2[h*Dn + dbase]);
                #pragma unroll
                for (int q = 0; q < 4; q++) {
                    ulonglong2 w = wp[q];
                    asm("fma.rn.f32x2 %0, %1, %2, %0;" : "+l"(accA[q][0]) : "l"(a0p), "l"(w.x));
                    asm("fma.rn.f32x2 %0, %1, %2, %0;" : "+l"(accA[q][1]) : "l"(a0p), "l"(w.y));
                    asm("fma.rn.f32x2 %0, %1, %2, %0;" : "+l"(accB[q][0]) : "l"(a1p), "l"(w.x));
                    asm("fma.rn.f32x2 %0, %1, %2, %0;" : "+l"(accB[q][1]) : "l"(a1p), "l"(w.y));
                }
            }
            #pragma unroll
            for (int q = 0; q < 4; q++) {
                #pragma unroll
                for (int hf = 0; hf < 2; hf++) {
                    int d = dbase + 4*q + 2*hf;
                    float lo, hi;
                    asm("mov.b64 {%0, %1}, %2;" : "=f"(lo), "=f"(hi) : "l"(accA[q][hf]));
                    float e0 = xs[sA*257+d+0]*rnA - lo;
                    float e1 = xs[sA*257+d+1]*rnA - hi;
                    aeacc += e0*e0 + e1*e1;
                    asm("mov.b64 {%0, %1}, %2;" : "=f"(lo), "=f"(hi) : "l"(accB[q][hf]));
                    float e2 = xs[sB*257+d+0]*rnB - lo;
                    float e3 = xs[sB*257+d+1]*rnB - hi;
                    aeacc += e2*e2 + e3*e3;
                }
            }
        }
    }
    __syncthreads();
    // block-reduce ae (reuse tp region as scratch)
    {
        float* aered = tp;
        aered[tid] = aeacc;
        __syncthreads();
        for (int off = 128; off > 0; off >>= 1) {
            if (tid < off) aered[tid] += aered[tid+off];
            __syncthreads();
        }
        if (tid == 0) atomicAdd(&g_ae, aered[0]);
    }
}

// ---------------- top-32 per concept over 65536 values ----------------
__global__ void k_topk() {
    __shared__ float cand[32*256];
    __shared__ float rv[256];
    __shared__ int   ri[256];
    int t = threadIdx.x, k = blockIdx.x;
    const float* src = g_tpn + (size_t)k*BS;

    float lv[32];
    #pragma unroll
    for (int i = 0; i < 32; i++) lv[i] = -3.4e38f;
    for (int i = 0; i < 256; i++) {
        float v = src[(i<<8) + t];           // coalesced
        if (v > lv[0]) {                      // sorted ascending insert
            int p = 0;
            while (p < 31 && lv[p+1] < v) { lv[p] = lv[p+1]; p++; }
            lv[p] = v;
        }
    }
    #pragma unroll
    for (int i = 0; i < 32; i++) cand[i*256 + t] = lv[i];
    __syncthreads();

    int ptr = 31;
    float lsum = 0.f;
    for (int r = 0; r < 32; r++) {
        rv[t] = (ptr >= 0) ? cand[ptr*256 + t] : -3.4e38f;
        ri[t] = t;
        __syncthreads();
        for (int off = 128; off > 0; off >>= 1) {
            if (t < off && rv[t+off] > rv[t]) { rv[t] = rv[t+off]; ri[t] = ri[t+off]; }
            __syncthreads();
        }
        if (t == 0) lsum += rv[0];
        int win = ri[0];
        __syncthreads();
        if (t == win) ptr--;
    }
    if (t == 0) atomicAdd(&g_sim, lsum);
}

// ---------------- finalization: pred + scalars ----------------
__global__ void k_final(const float* __restrict__ rv2, const float* __restrict__ Wc,
                        const float* __restrict__ bc, float* __restrict__ out) {
    __shared__ float w2c[Hn*NC];
    int t = threadIdx.x;   // 512 threads
    {
        int h = t >> 1, c = t & 1;
        float a = 0.f;
        for (int d = 0; d < Dn; d++) a += rv2[h*Dn + d] * Wc[d*NC + c];
        w2c[t] = a;        // [h][c]
    }
    __syncthreads();
    if (t < Bn*NC) {
        int b = t >> 1, c = t & 1;
        float p = 0.f;
        for (int h = 0; h < Hn; h++) p += g_acc1[b*Hn + h] * w2c[h*NC + c];
        out[t] = p * (1.0f/(float)Sn) + bc[c];
    }
    if (t == 256) out[256] = 0.f;
    if (t == 257) out[257] = -g_sim * (1.0f/(float)(Kn * (Bn/4)));
    if (t == 258) out[OUT_AE] = g_ae * (1.0f/(float)(Bn*Sn*Dn));
}

// ---------------- launch ----------------
extern "C" void kernel_launch(void* const* d_in, const int* in_sizes, int n_in,
                              void* d_out, int out_size) {
    const float* f   = (const float*)d_in[0];
    // d_in[1] = targets (unused by reference outputs)
    const float* tv  = (const float*)d_in[2];
    const float* rv1 = (const float*)d_in[3];
    const float* rv2 = (const float*)d_in[4];
    const float* Wc  = (const float*)d_in[5];
    const float* bc  = (const float*)d_in[6];
    // d_in[7] = causal (unused, = 0)
    float* out = (float*)d_out;

    k_init<<<128, 256>>>();
    k_prep<<<50, 256>>>(tv);
    k_far<<<1, 256>>>(out);

    cudaFuncSetAttribute(k_main, cudaFuncAttributeMaxDynamicSharedMemorySize,
                         SM_TOT * (int)sizeof(float));
    k_main<<<dim3(8, 128), 256, SM_TOT * sizeof(float)>>>(f, rv1, rv2, out);

    k_topk<<<50, 256>>>();
    k_final<<<1, 512>>>(rv2, Wc, bc, out);
}

// round 5
// speedup vs baseline: 1.3145x; 1.3145x over previous
#include <cuda_runtime.h>
#include <math.h>

// Problem constants
#define Bn   128
#define Dn   256
#define Sn   512
#define Kn   50
#define Hn   256
#define NC   2
#define THRES 0.3f
#define BS   (Bn*Sn)          // 65536

// Output layout (float32, concatenated tuple):
//  [0..255]       pred [B,NC]
//  [256]          0.0
//  [257]          concept_sim
//  [258]          concept_far
//  [259..+B*S*K)  topic_prob_nn [B,S,K]
//  [3277059]      ae_loss
#define OUT_NN   259
#define OUT_AE   (259 + Bn*Sn*Kn)   // 3277059

// ---------------- device scratch ----------------
__device__ float g_tvnT[Kn*Dn];            // normalized topic vectors, [K][D]
__device__ float g_tpn[(size_t)Kn*BS];     // topic_prob_n, [K][B*S]   (13.1 MB)
__device__ float g_xn[(size_t)BS*Dn];      // x_n, [B*S][D]            (64 MB)
__device__ float g_r1[(size_t)BS*Hn];      // relu(rec1), [B*S][H]     (64 MB)
__device__ float g_acc1[Bn*Hn];            // sum over s of rec1
__device__ float g_ae;
__device__ float g_sim;

// ---------------- init ----------------
__global__ void k_init() {
    int i = blockIdx.x*blockDim.x + threadIdx.x;
    if (i < Bn*Hn) g_acc1[i] = 0.f;
    if (i == 0) { g_ae = 0.f; g_sim = 0.f; }
}

// ---------------- tv normalization ----------------
__global__ void k_prep(const float* __restrict__ tv) {
    __shared__ float sred[256];
    int k = blockIdx.x, d = threadIdx.x;
    float v = tv[d*Kn + k];
    sred[d] = v*v;
    __syncthreads();
    for (int off = 128; off > 0; off >>= 1) {
        if (d < off) sred[d] += sred[d+off];
        __syncthreads();
    }
    float nrm = sqrtf(sred[0]);
    g_tvnT[k*Dn + d] = v / fmaxf(nrm, 1e-12f);
}

// ---------------- concept_far = (||sum_k tvn_k||^2 - K) / K^2 ----------------
__global__ void k_far(float* __restrict__ out) {
    __shared__ float sred[256];
    int d = threadIdx.x;
    float u = 0.f;
    for (int k = 0; k < Kn; k++) u += g_tvnT[k*Dn + d];
    sred[d] = u*u;
    __syncthreads();
    for (int off = 128; off > 0; off >>= 1) {
        if (d < off) sred[d] += sred[d+off];
        __syncthreads();
    }
    if (d == 0) out[258] = (sred[0] - (float)Kn) / (float)(Kn*Kn);
}

// ================= Kernel 1: topic path =================
// grid (16, 128): 32 s-positions per block, 256 threads.
__global__ void __launch_bounds__(256, 2)
k_topic(const float* __restrict__ f, float* __restrict__ out)
{
    __shared__ float xs[32*257];
    __shared__ float tp[32*51];
    __shared__ float red[256];
    __shared__ float rn[32];
    __shared__ float inv[32];

    const int tid = threadIdx.x;
    const int b = blockIdx.y;
    const int s0 = blockIdx.x * 32;
    const int bs0 = b*Sn + s0;

    // coalesced load: f is [B,D,S]
    const float* fb = f + (size_t)b*Dn*Sn + s0;
    for (int i = tid; i < 32*Dn; i += 256) {
        int d = i >> 5, sl = i & 31;
        xs[sl*257 + d] = fb[(size_t)d*Sn + sl];
    }
    __syncthreads();

    // per-s inverse norms
    {
        int s = tid & 31, part = tid >> 5;
        float a = 0.f;
        int d0 = part*32;
        #pragma unroll 8
        for (int d = d0; d < d0+32; d++) { float v = xs[s*257+d]; a += v*v; }
        red[part*32 + s] = a;
    }
    __syncthreads();
    if (tid < 32) {
        float nsq = 0.f;
        #pragma unroll
        for (int p = 0; p < 8; p++) nsq += red[p*32 + tid];
        rn[tid] = 1.0f / fmaxf(sqrtf(nsq), 1e-12f);
    }
    __syncthreads();

    // write x_n scratch, coalesced [bs][d]
    for (int i = tid; i < 32*Dn; i += 256) {
        int sl = i >> 8, d = i & 255;
        g_xn[(size_t)(bs0+sl)*Dn + d] = xs[sl*257+d] * rn[sl];
    }

    // topic_prob: thread (s = tid&31, kg = tid>>5) handles k = kg + 8j
    const int s = tid & 31, kg = tid >> 5;
    float acc[7];
    #pragma unroll
    for (int j = 0; j < 7; j++) acc[j] = 0.f;
    for (int d = 0; d < Dn; d += 4) {
        float x0 = xs[s*257+d+0], x1 = xs[s*257+d+1];
        float x2 = xs[s*257+d+2], x3 = xs[s*257+d+3];
        #pragma unroll
        for (int j = 0; j < 7; j++) {
            int k = kg + 8*j;
            int kc = (k < Kn) ? k : 0;                    // clamp (result unused if !ok)
            const float4 w = *reinterpret_cast<const float4*>(&g_tvnT[kc*Dn + d]);
            acc[j] += x0*w.x + x1*w.y + x2*w.z + x3*w.w;
        }
    }

    // threshold mask + per-s sum
    float am[7];
    {
        float rns = rn[s];
        float psum = 0.f;
        #pragma unroll
        for (int j = 0; j < 7; j++) {
            int k = kg + 8*j;
            if (k < Kn) {
                float tn = acc[j] * rns;
                g_tpn[(size_t)k*BS + bs0 + s] = tn;       // lanes -> consecutive bs
                am[j] = (tn > THRES) ? acc[j] : 0.f;
                psum += am[j];
            } else am[j] = 0.f;
        }
        red[kg*32 + s] = psum;
    }
    __syncthreads();
    if (tid < 32) {
        float t = 0.f;
        #pragma unroll
        for (int p = 0; p < 8; p++) t += red[p*32 + tid];
        inv[tid] = 1.0f / (t + 0.001f + 1e-8f);
    }
    __syncthreads();
    {
        float iv = inv[s];
        #pragma unroll
        for (int j = 0; j < 7; j++) {
            int k = kg + 8*j;
            if (k < Kn) tp[s*51 + k] = am[j] * iv;
        }
    }
    __syncthreads();

    // write topic_prob_nn to out, coalesced
    {
        float* onn = out + OUT_NN + (size_t)bs0 * Kn;
        for (int i = tid; i < 32*Kn; i += 256) {
            int ss = i / 50, k = i - ss*50;
            onn[i] = tp[ss*51 + k];
        }
    }
}

// ================= Kernel 2: rec1 GEMM [65536,50]x[50,256] =================
// grid 1024, 256 threads; block = 64 bs-rows x 256 h.
// dynamic smem: w1[50*256] | a_t[64*52]
#define RS1_FLOATS (Kn*Hn + 64*52)
__global__ void __launch_bounds__(256, 2)
k_rec1(const float* __restrict__ rv1, const float* __restrict__ out)
{
    extern __shared__ float sm1[];
    float* w1  = sm1;                 // [50][256]
    float* a_t = sm1 + Kn*Hn;         // [64][52]

    const int tid = threadIdx.x;
    const int bs0 = blockIdx.x * 64;
    const int wid = tid >> 5, lane = tid & 31;
    const int d0 = lane * 8;

    for (int i = tid; i < Kn*Hn; i += 256) w1[i] = rv1[i];
    {
        const float* nnsrc = out + OUT_NN + (size_t)bs0 * Kn;
        for (int i = tid; i < 64*Kn; i += 256) {
            int ss = i / 50, k = i - ss*50;
            a_t[ss*52 + k] = nnsrc[i];
        }
    }
    __syncthreads();

    unsigned long long acc[8][4];
    #pragma unroll
    for (int j = 0; j < 8; j++)
        #pragma unroll
        for (int q = 0; q < 4; q++) acc[j][q] = 0ull;

    #pragma unroll 5
    for (int k2 = 0; k2 < Kn; k2 += 2) {
        float2 av[8];
        #pragma unroll
        for (int j = 0; j < 8; j++)
            av[j] = *reinterpret_cast<const float2*>(&a_t[(8*wid+j)*52 + k2]);
        #pragma unroll
        for (int kk = 0; kk < 2; kk++) {
            const ulonglong2 wa = *reinterpret_cast<const ulonglong2*>(&w1[(k2+kk)*Hn + d0]);
            const ulonglong2 wb = *reinterpret_cast<const ulonglong2*>(&w1[(k2+kk)*Hn + d0 + 4]);
            #pragma unroll
            for (int j = 0; j < 8; j++) {
                float aj = kk ? av[j].y : av[j].x;
                unsigned long long ap;
                asm("mov.b64 %0, {%1, %1};" : "=l"(ap) : "f"(aj));
                asm("fma.rn.f32x2 %0, %1, %2, %0;" : "+l"(acc[j][0]) : "l"(ap), "l"(wa.x));
                asm("fma.rn.f32x2 %0, %1, %2, %0;" : "+l"(acc[j][1]) : "l"(ap), "l"(wa.y));
                asm("fma.rn.f32x2 %0, %1, %2, %0;" : "+l"(acc[j][2]) : "l"(ap), "l"(wb.x));
                asm("fma.rn.f32x2 %0, %1, %2, %0;" : "+l"(acc[j][3]) : "l"(ap), "l"(wb.y));
            }
        }
    }

    // relu, store r1, accumulate per-h column sums
    float hs[8];
    #pragma unroll
    for (int i = 0; i < 8; i++) hs[i] = 0.f;
    #pragma unroll
    for (int j = 0; j < 8; j++) {
        float v[8];
        #pragma unroll
        for (int q = 0; q < 4; q++) {
            float lo, hi;
            asm("mov.b64 {%0, %1}, %2;" : "=f"(lo), "=f"(hi) : "l"(acc[j][q]));
            v[2*q]   = fmaxf(lo, 0.f);
            v[2*q+1] = fmaxf(hi, 0.f);
        }
        #pragma unroll
        for (int i = 0; i < 8; i++) hs[i] += v[i];
        size_t base = (size_t)(bs0 + 8*wid + j)*Hn + d0;
        *reinterpret_cast<float4*>(&g_r1[base])   = make_float4(v[0],v[1],v[2],v[3]);
        *reinterpret_cast<float4*>(&g_r1[base+4]) = make_float4(v[4],v[5],v[6],v[7]);
    }
    int b = bs0 >> 9;
    #pragma unroll
    for (int i = 0; i < 8; i++)
        atomicAdd(&g_acc1[b*Hn + d0 + i], hs[i]);
}

// ================= Kernel 3: rec2 GEMM [65536,256]x[256,256] + ae fused =================
// grid 1024, 256 threads; block = 64 bs-rows x 256 d; h staged in chunks of 32.
__global__ void __launch_bounds__(256, 2)
k_rec2ae(const float* __restrict__ rv2)
{
    __shared__ float a_t[64*36];      // [64 s][32 h] padded
    __shared__ float w_t[32*260];     // [32 h][256 d] padded

    const int tid = threadIdx.x;
    const int bs0 = blockIdx.x * 64;
    const int wid = tid >> 5, lane = tid & 31;
    const int d0 = lane * 8;

    unsigned long long acc[8][4];
    #pragma unroll
    for (int j = 0; j < 8; j++)
        #pragma unroll
        for (int q = 0; q < 4; q++) acc[j][q] = 0ull;

    for (int hc = 0; hc < Hn; hc += 32) {
        // stage r1 tile [64][32]
        for (int i = tid; i < 64*32; i += 256) {
            int r = i >> 5, c = i & 31;
            a_t[r*36 + c] = g_r1[(size_t)(bs0 + r)*Hn + hc + c];
        }
        // stage rv2 tile [32][256]
        for (int i = tid; i < 32*Dn; i += 256) {
            int r = i >> 8, d = i & 255;
            w_t[r*260 + d] = rv2[(hc + r)*Dn + d];
        }
        __syncthreads();

        #pragma unroll 4
        for (int k2 = 0; k2 < 32; k2 += 2) {
            float2 av[8];
            #pragma unroll
            for (int j = 0; j < 8; j++)
                av[j] = *reinterpret_cast<const float2*>(&a_t[(8*wid+j)*36 + k2]);
            #pragma unroll
            for (int kk = 0; kk < 2; kk++) {
                const ulonglong2 wa = *reinterpret_cast<const ulonglong2*>(&w_t[(k2+kk)*260 + d0]);
                const ulonglong2 wb = *reinterpret_cast<const ulonglong2*>(&w_t[(k2+kk)*260 + d0 + 4]);
                #pragma unroll
                for (int j = 0; j < 8; j++) {
                    float aj = kk ? av[j].y : av[j].x;
                    unsigned long long ap;
                    asm("mov.b64 %0, {%1, %1};" : "=l"(ap) : "f"(aj));
                    asm("fma.rn.f32x2 %0, %1, %2, %0;" : "+l"(acc[j][0]) : "l"(ap), "l"(wa.x));
                    asm("fma.rn.f32x2 %0, %1, %2, %0;" : "+l"(acc[j][1]) : "l"(ap), "l"(wa.y));
                    asm("fma.rn.f32x2 %0, %1, %2, %0;" : "+l"(acc[j][2]) : "l"(ap), "l"(wb.x));
                    asm("fma.rn.f32x2 %0, %1, %2, %0;" : "+l"(acc[j][3]) : "l"(ap), "l"(wb.y));
                }
            }
        }
        __syncthreads();
    }

    // epilogue: ae accumulation only (rec2 never materialized)
    float aeacc = 0.f;
    #pragma unroll
    for (int j = 0; j < 8; j++) {
        size_t base = (size_t)(bs0 + 8*wid + j)*Dn + d0;
        float4 xa = *reinterpret_cast<const float4*>(&g_xn[base]);
        float4 xb = *reinterpret_cast<const float4*>(&g_xn[base+4]);
        float lo, hi, e;
        asm("mov.b64 {%0, %1}, %2;" : "=f"(lo), "=f"(hi) : "l"(acc[j][0]));
        e = xa.x - lo; aeacc += e*e;  e = xa.y - hi; aeacc += e*e;
        asm("mov.b64 {%0, %1}, %2;" : "=f"(lo), "=f"(hi) : "l"(acc[j][1]));
        e = xa.z - lo; aeacc += e*e;  e = xa.w - hi; aeacc += e*e;
        asm("mov.b64 {%0, %1}, %2;" : "=f"(lo), "=f"(hi) : "l"(acc[j][2]));
        e = xb.x - lo; aeacc += e*e;  e = xb.y - hi; aeacc += e*e;
        asm("mov.b64 {%0, %1}, %2;" : "=f"(lo), "=f"(hi) : "l"(acc[j][3]));
        e = xb.z - lo; aeacc += e*e;  e = xb.w - hi; aeacc += e*e;
    }
    #pragma unroll
    for (int off = 16; off > 0; off >>= 1)
        aeacc += __shfl_xor_sync(0xffffffffu, aeacc, off);
    if (lane == 0) atomicAdd(&g_ae, aeacc);
}

// ---------------- top-32 per concept over 65536 values ----------------
__global__ void k_topk() {
    __shared__ float cand[32*256];
    __shared__ float rv[256];
    __shared__ int   ri[256];
    int t = threadIdx.x, k = blockIdx.x;
    const float* src = g_tpn + (size_t)k*BS;

    float lv[32];
    #pragma unroll
    for (int i = 0; i < 32; i++) lv[i] = -3.4e38f;
    for (int i = 0; i < 256; i++) {
        float v = src[(i<<8) + t];
        if (v > lv[0]) {
            int p = 0;
            while (p < 31 && lv[p+1] < v) { lv[p] = lv[p+1]; p++; }
            lv[p] = v;
        }
    }
    #pragma unroll
    for (int i = 0; i < 32; i++) cand[i*256 + t] = lv[i];
    __syncthreads();

    int ptr = 31;
    float lsum = 0.f;
    for (int r = 0; r < 32; r++) {
        rv[t] = (ptr >= 0) ? cand[ptr*256 + t] : -3.4e38f;
        ri[t] = t;
        __syncthreads();
        for (int off = 128; off > 0; off >>= 1) {
            if (t < off && rv[t+off] > rv[t]) { rv[t] = rv[t+off]; ri[t] = ri[t+off]; }
            __syncthreads();
        }
        if (t == 0) lsum += rv[0];
        int win = ri[0];
        __syncthreads();
        if (t == win) ptr--;
    }
    if (t == 0) atomicAdd(&g_sim, lsum);
}

// ---------------- finalization: pred + scalars ----------------
__global__ void k_final(const float* __restrict__ rv2, const float* __restrict__ Wc,
                        const float* __restrict__ bc, float* __restrict__ out) {
    __shared__ float w2c[Hn*NC];
    int t = threadIdx.x;   // 512 threads
    {
        int h = t >> 1, c = t & 1;
        float a = 0.f;
        for (int d = 0; d < Dn; d++) a += rv2[h*Dn + d] * Wc[d*NC + c];
        w2c[t] = a;
    }
    __syncthreads();
    if (t < Bn*NC) {
        int b = t >> 1, c = t & 1;
        float p = 0.f;
        for (int h = 0; h < Hn; h++) p += g_acc1[b*Hn + h] * w2c[h*NC + c];
        out[t] = p * (1.0f/(float)Sn) + bc[c];
    }
    if (t == 256) out[256] = 0.f;
    if (t == 257) out[257] = -g_sim * (1.0f/(float)(Kn * (Bn/4)));
    if (t == 258) out[OUT_AE] = g_ae * (1.0f/(float)(Bn*Sn*Dn));
}

// ---------------- launch ----------------
extern "C" void kernel_launch(void* const* d_in, const int* in_sizes, int n_in,
                              void* d_out, int out_size) {
    const float* f   = (const float*)d_in[0];
    const float* tv  = (const float*)d_in[2];
    const float* rv1 = (const float*)d_in[3];
    const float* rv2 = (const float*)d_in[4];
    const float* Wc  = (const float*)d_in[5];
    const float* bc  = (const float*)d_in[6];
    float* out = (float*)d_out;

    k_init<<<128, 256>>>();
    k_prep<<<50, 256>>>(tv);
    k_far<<<1, 256>>>(out);

    k_topic<<<dim3(16, 128), 256>>>(f, out);

    k_topk<<<50, 256>>>();

    static int rs1_set = 0;
    if (!rs1_set) {
        cudaFuncSetAttribute(k_rec1, cudaFuncAttributeMaxDynamicSharedMemorySize,
                             RS1_FLOATS * (int)sizeof(float));
        rs1_set = 1;
    }
    k_rec1<<<1024, 256, RS1_FLOATS * sizeof(float)>>>(rv1, out);

    k_rec2ae<<<1024, 256>>>(rv2);

    k_final<<<1, 512>>>(rv2, Wc, bc, out);
}

// round 6
// speedup vs baseline: 1.7233x; 1.3110x over previous
#include <cuda_runtime.h>
#include <math.h>

// Problem constants
#define Bn   128
#define Dn   256
#define Sn   512
#define Kn   50
#define Hn   256
#define NC   2
#define THRES 0.3f
#define BS   (Bn*Sn)          // 65536

// Output layout (float32):
//  [0..255] pred | [256] 0 | [257] concept_sim | [258] concept_far
//  [259..+B*S*K) topic_prob_nn | [3277059] ae_loss
#define OUT_NN   259
#define OUT_AE   (259 + Bn*Sn*Kn)   // 3277059

// ---------------- device scratch ----------------
__device__ float g_tvnT[Kn*Dn];            // normalized topic vectors, [K][D]
__device__ float g_tpn[(size_t)Kn*BS];     // topic_prob_n, [K][B*S]  (13.1 MB)
__device__ float g_xn[(size_t)BS*Dn];      // x_n, [B*S][D]           (64 MB)
__device__ float g_acc1[Bn*Hn];            // sum over s of rec1
__device__ float g_cand[Kn*128];           // per-part top-32 candidates
__device__ float g_ae;

// ---------------- init ----------------
__global__ void k_init() {
    int i = blockIdx.x*blockDim.x + threadIdx.x;
    if (i < Bn*Hn) g_acc1[i] = 0.f;
    if (i == 0) g_ae = 0.f;
}

// ---------------- tv normalization ----------------
__global__ void k_prep(const float* __restrict__ tv) {
    __shared__ float sred[256];
    int k = blockIdx.x, d = threadIdx.x;
    float v = tv[d*Kn + k];
    sred[d] = v*v;
    __syncthreads();
    for (int off = 128; off > 0; off >>= 1) {
        if (d < off) sred[d] += sred[d+off];
        __syncthreads();
    }
    float nrm = sqrtf(sred[0]);
    g_tvnT[k*Dn + d] = v / fmaxf(nrm, 1e-12f);
}

// ---------------- concept_far = (||sum_k tvn_k||^2 - K) / K^2 ----------------
__global__ void k_far(float* __restrict__ out) {
    __shared__ float sred[256];
    int d = threadIdx.x;
    float u = 0.f;
    for (int k = 0; k < Kn; k++) u += g_tvnT[k*Dn + d];
    sred[d] = u*u;
    __syncthreads();
    for (int off = 128; off > 0; off >>= 1) {
        if (d < off) sred[d] += sred[d+off];
        __syncthreads();
    }
    if (d == 0) out[258] = (sred[0] - (float)Kn) / (float)(Kn*Kn);
}

// ================= Kernel 1: topic path =================
// grid (8, 128): 64 s per block, 512 threads, 2 blocks/SM.
// dyn smem floats: xs[64][257] | tp[64][51] | red[512] | rn[64] | inv[64]
#define T_XS   0
#define T_TP   16448
#define T_RED  19712
#define T_RN   20224
#define T_INV  20288
#define T_TOT  20352      // floats -> 81408 bytes
__global__ void __launch_bounds__(512, 2)
k_topic(const float* __restrict__ f, float* __restrict__ out)
{
    extern __shared__ float sm[];
    float* xs  = sm + T_XS;
    float* tp  = sm + T_TP;
    float* red = sm + T_RED;
    float* rn  = sm + T_RN;
    float* inv = sm + T_INV;

    const int tid = threadIdx.x;
    const int b = blockIdx.y;
    const int s0 = blockIdx.x * 64;
    const int bs0 = b*Sn + s0;

    // coalesced load: f is [B,D,S]
    const float* fb = f + (size_t)b*Dn*Sn + s0;
    for (int i = tid; i < 64*Dn; i += 512) {
        int d = i >> 6, sl = i & 63;
        xs[sl*257 + d] = fb[(size_t)d*Sn + sl];
    }
    __syncthreads();

    // per-s inverse norms (8 partials of 32 d each)
    {
        int s = tid & 63, part = tid >> 6;
        float a = 0.f;
        int d0 = part*32;
        #pragma unroll 8
        for (int d = d0; d < d0+32; d++) { float v = xs[s*257+d]; a += v*v; }
        red[part*64 + s] = a;
    }
    __syncthreads();
    if (tid < 64) {
        float nsq = 0.f;
        #pragma unroll
        for (int p = 0; p < 8; p++) nsq += red[p*64 + tid];
        rn[tid] = 1.0f / fmaxf(sqrtf(nsq), 1e-12f);
    }
    __syncthreads();

    // write x_n scratch, coalesced [bs][d]
    for (int i = tid; i < 64*Dn; i += 512) {
        int sl = i >> 8, d = i & 255;
        g_xn[(size_t)(bs0+sl)*Dn + d] = xs[sl*257+d] * rn[sl];
    }

    // topic_prob: thread (s = tid&63, kg = tid>>6) handles k = kg + 8j
    const int s = tid & 63, kg = tid >> 6;
    float acc[7];
    #pragma unroll
    for (int j = 0; j < 7; j++) acc[j] = 0.f;
    for (int d = 0; d < Dn; d += 4) {
        float x0 = xs[s*257+d+0], x1 = xs[s*257+d+1];
        float x2 = xs[s*257+d+2], x3 = xs[s*257+d+3];
        #pragma unroll
        for (int j = 0; j < 7; j++) {
            int k = kg + 8*j;
            int kc = (k < Kn) ? k : 0;
            const float4 w = *reinterpret_cast<const float4*>(&g_tvnT[kc*Dn + d]);
            acc[j] += x0*w.x + x1*w.y + x2*w.z + x3*w.w;
        }
    }

    // threshold mask + per-s sum
    float am[7];
    {
        float rns = rn[s];
        float psum = 0.f;
        #pragma unroll
        for (int j = 0; j < 7; j++) {
            int k = kg + 8*j;
            if (k < Kn) {
                float tn = acc[j] * rns;
                g_tpn[(size_t)k*BS + bs0 + s] = tn;
                am[j] = (tn > THRES) ? acc[j] : 0.f;
                psum += am[j];
            } else am[j] = 0.f;
        }
        red[kg*64 + s] = psum;
    }
    __syncthreads();
    if (tid < 64) {
        float t = 0.f;
        #pragma unroll
        for (int p = 0; p < 8; p++) t += red[p*64 + tid];
        inv[tid] = 1.0f / (t + 0.001f + 1e-8f);
    }
    __syncthreads();
    {
        float iv = inv[s];
        #pragma unroll
        for (int j = 0; j < 7; j++) {
            int k = kg + 8*j;
            if (k < Kn) tp[s*51 + k] = am[j] * iv;
        }
    }
    __syncthreads();

    // write topic_prob_nn to out, coalesced
    {
        float* onn = out + OUT_NN + (size_t)bs0 * Kn;
        for (int i = tid; i < 64*Kn; i += 512) {
            int ss = i / 50, k = i - ss*50;
            onn[i] = tp[ss*51 + k];
        }
    }
}

// ================= Kernel 2: fused rec1 + rec2 + ae =================
// grid 1024, 256 threads; block = 64 bs-rows. Weights streamed via broadcast LDG.
// dyn smem floats: nn_t[64][52] | r1[64][260]
#define R_NN   0
#define R_R1   (64*52)
#define R_TOT  (64*52 + 64*260)   // 19968 floats -> 79872 bytes
__global__ void __launch_bounds__(256, 2)
k_rec(const float* __restrict__ rv1, const float* __restrict__ rv2,
      const float* __restrict__ out)
{
    extern __shared__ float smr[];
    float* nn_t = smr + R_NN;     // [64][52]
    float* r1   = smr + R_R1;     // [64][260]

    const int tid = threadIdx.x;
    const int bs0 = blockIdx.x * 64;
    const int wid = tid >> 5, lane = tid & 31;
    const int d0 = lane * 8;

    // stage nn tile
    {
        const float* nnsrc = out + OUT_NN + (size_t)bs0 * Kn;
        for (int i = tid; i < 64*Kn; i += 256) {
            int ss = i / 50, k = i - ss*50;
            nn_t[ss*52 + k] = nnsrc[i];
        }
    }
    __syncthreads();

    // ---- rec1: [64,50] x [50,256], weights via broadcast LDG ----
    {
        unsigned long long acc[8][4];
        #pragma unroll
        for (int j = 0; j < 8; j++)
            #pragma unroll
            for (int q = 0; q < 4; q++) acc[j][q] = 0ull;

        #pragma unroll 5
        for (int k2 = 0; k2 < Kn; k2 += 2) {
            float2 av[8];
            #pragma unroll
            for (int j = 0; j < 8; j++)
                av[j] = *reinterpret_cast<const float2*>(&nn_t[(8*wid+j)*52 + k2]);
            #pragma unroll
            for (int kk = 0; kk < 2; kk++) {
                const ulonglong2 wa = *reinterpret_cast<const ulonglong2*>(&rv1[(k2+kk)*Hn + d0]);
                const ulonglong2 wb = *reinterpret_cast<const ulonglong2*>(&rv1[(k2+kk)*Hn + d0 + 4]);
                #pragma unroll
                for (int j = 0; j < 8; j++) {
                    float aj = kk ? av[j].y : av[j].x;
                    unsigned long long ap;
                    asm("mov.b64 %0, {%1, %1};" : "=l"(ap) : "f"(aj));
                    asm("fma.rn.f32x2 %0, %1, %2, %0;" : "+l"(acc[j][0]) : "l"(ap), "l"(wa.x));
                    asm("fma.rn.f32x2 %0, %1, %2, %0;" : "+l"(acc[j][1]) : "l"(ap), "l"(wa.y));
                    asm("fma.rn.f32x2 %0, %1, %2, %0;" : "+l"(acc[j][2]) : "l"(ap), "l"(wb.x));
                    asm("fma.rn.f32x2 %0, %1, %2, %0;" : "+l"(acc[j][3]) : "l"(ap), "l"(wb.y));
                }
            }
        }

        // relu -> r1 smem; per-h column sums -> g_acc1
        float hs[8];
        #pragma unroll
        for (int i = 0; i < 8; i++) hs[i] = 0.f;
        #pragma unroll
        for (int j = 0; j < 8; j++) {
            float v[8];
            #pragma unroll
            for (int q = 0; q < 4; q++) {
                float lo, hi;
                asm("mov.b64 {%0, %1}, %2;" : "=f"(lo), "=f"(hi) : "l"(acc[j][q]));
                v[2*q]   = fmaxf(lo, 0.f);
                v[2*q+1] = fmaxf(hi, 0.f);
            }
            #pragma unroll
            for (int i = 0; i < 8; i++) hs[i] += v[i];
            float* dst = &r1[(8*wid+j)*260 + d0];
            *reinterpret_cast<float4*>(dst)     = make_float4(v[0],v[1],v[2],v[3]);
            *reinterpret_cast<float4*>(dst + 4) = make_float4(v[4],v[5],v[6],v[7]);
        }
        int b = bs0 >> 9;
        #pragma unroll
        for (int i = 0; i < 8; i++)
            atomicAdd(&g_acc1[b*Hn + d0 + i], hs[i]);
    }
    __syncthreads();

    // ---- rec2: [64,256] x [256,256], weights via broadcast LDG, ae fused ----
    unsigned long long acc[8][4];
    #pragma unroll
    for (int j = 0; j < 8; j++)
        #pragma unroll
        for (int q = 0; q < 4; q++) acc[j][q] = 0ull;

    #pragma unroll 4
    for (int k2 = 0; k2 < Hn; k2 += 2) {
        float2 av[8];
        #pragma unroll
        for (int j = 0; j < 8; j++)
            av[j] = *reinterpret_cast<const float2*>(&r1[(8*wid+j)*260 + k2]);
        #pragma unroll
        for (int kk = 0; kk < 2; kk++) {
            const ulonglong2 wa = *reinterpret_cast<const ulonglong2*>(&rv2[(k2+kk)*Dn + d0]);
            const ulonglong2 wb = *reinterpret_cast<const ulonglong2*>(&rv2[(k2+kk)*Dn + d0 + 4]);
            #pragma unroll
            for (int j = 0; j < 8; j++) {
                float aj = kk ? av[j].y : av[j].x;
                unsigned long long ap;
                asm("mov.b64 %0, {%1, %1};" : "=l"(ap) : "f"(aj));
                asm("fma.rn.f32x2 %0, %1, %2, %0;" : "+l"(acc[j][0]) : "l"(ap), "l"(wa.x));
                asm("fma.rn.f32x2 %0, %1, %2, %0;" : "+l"(acc[j][1]) : "l"(ap), "l"(wa.y));
                asm("fma.rn.f32x2 %0, %1, %2, %0;" : "+l"(acc[j][2]) : "l"(ap), "l"(wb.x));
                asm("fma.rn.f32x2 %0, %1, %2, %0;" : "+l"(acc[j][3]) : "l"(ap), "l"(wb.y));
            }
        }
    }

    // ae epilogue (rec2 never materialized)
    float aeacc = 0.f;
    #pragma unroll
    for (int j = 0; j < 8; j++) {
        size_t base = (size_t)(bs0 + 8*wid + j)*Dn + d0;
        float4 xa = *reinterpret_cast<const float4*>(&g_xn[base]);
        float4 xb = *reinterpret_cast<const float4*>(&g_xn[base+4]);
        float lo, hi, e;
        asm("mov.b64 {%0, %1}, %2;" : "=f"(lo), "=f"(hi) : "l"(acc[j][0]));
        e = xa.x - lo; aeacc += e*e;  e = xa.y - hi; aeacc += e*e;
        asm("mov.b64 {%0, %1}, %2;" : "=f"(lo), "=f"(hi) : "l"(acc[j][1]));
        e = xa.z - lo; aeacc += e*e;  e = xa.w - hi; aeacc += e*e;
        asm("mov.b64 {%0, %1}, %2;" : "=f"(lo), "=f"(hi) : "l"(acc[j][2]));
        e = xb.x - lo; aeacc += e*e;  e = xb.y - hi; aeacc += e*e;
        asm("mov.b64 {%0, %1}, %2;" : "=f"(lo), "=f"(hi) : "l"(acc[j][3]));
        e = xb.z - lo; aeacc += e*e;  e = xb.w - hi; aeacc += e*e;
    }
    #pragma unroll
    for (int off = 16; off > 0; off >>= 1)
        aeacc += __shfl_xor_sync(0xffffffffu, aeacc, off);
    if (lane == 0) atomicAdd(&g_ae, aeacc);
}

// ---------------- topk part: top-32 of 16384 per (concept, quarter) ----------------
__global__ void k_topk_part() {
    __shared__ float cand[32*256];
    __shared__ float rv[256];
    __shared__ int   ri[256];
    int t = threadIdx.x, k = blockIdx.x, part = blockIdx.y;
    const float* src = g_tpn + (size_t)k*BS + part*16384;

    float lv[32];
    #pragma unroll
    for (int i = 0; i < 32; i++) lv[i] = -3.4e38f;
    for (int i = 0; i < 64; i++) {
        float v = src[(i<<8) + t];
        if (v > lv[0]) {
            int p = 0;
            while (p < 31 && lv[p+1] < v) { lv[p] = lv[p+1]; p++; }
            lv[p] = v;
        }
    }
    #pragma unroll
    for (int i = 0; i < 32; i++) cand[i*256 + t] = lv[i];
    __syncthreads();

    int ptr = 31;
    for (int r = 0; r < 32; r++) {
        rv[t] = (ptr >= 0) ? cand[ptr*256 + t] : -3.4e38f;
        ri[t] = t;
        __syncthreads();
        for (int off = 128; off > 0; off >>= 1) {
            if (t < off && rv[t+off] > rv[t]) { rv[t] = rv[t+off]; ri[t] = ri[t+off]; }
            __syncthreads();
        }
        if (t == 0) g_cand[k*128 + part*32 + r] = rv[0];   // descending order
        int win = ri[0];
        __syncthreads();
        if (t == win) ptr--;
    }
}

// ---------------- topk merge: 4-way merge of sorted 32-lists, writes concept_sim ----
__global__ void k_topk_merge(float* __restrict__ out) {
    __shared__ float vals[Kn*130];
    __shared__ float sred[64];
    int t = threadIdx.x;  // 64 threads
    for (int i = t; i < Kn*128; i += 64) {
        int k = i >> 7, r = i & 127;
        vals[k*130 + r] = g_cand[i];
    }
    __syncthreads();
    float lsum = 0.f;
    if (t < Kn) {
        const float* row = &vals[t*130];
        int p0 = 0, p1 = 0, p2 = 0, p3 = 0;
        for (int r = 0; r < 32; r++) {
            float v0 = (p0 < 32) ? row[p0]      : -3.4e38f;
            float v1 = (p1 < 32) ? row[32+p1]   : -3.4e38f;
            float v2 = (p2 < 32) ? row[64+p2]   : -3.4e38f;
            float v3 = (p3 < 32) ? row[96+p3]   : -3.4e38f;
            float m01 = fmaxf(v0, v1), m23 = fmaxf(v2, v3);
            float m = fmaxf(m01, m23);
            lsum += m;
            if (m == v0)      p0++;
            else if (m == v1) p1++;
            else if (m == v2) p2++;
            else              p3++;
        }
    }
    sred[t] = lsum;
    __syncthreads();
    for (int off = 32; off > 0; off >>= 1) {
        if (t < off) sred[t] += sred[t+off];
        __syncthreads();
    }
    if (t == 0) out[257] = -sred[0] * (1.0f/(float)(Kn * (Bn/4)));
}

// ---------------- finalization: pred + remaining scalars ----------------
__global__ void k_final(const float* __restrict__ rv2, const float* __restrict__ Wc,
                        const float* __restrict__ bc, float* __restrict__ out) {
    __shared__ float w2c[Hn*NC];
    int t = threadIdx.x;   // 512 threads
    {
        int h = t >> 1, c = t & 1;
        float a = 0.f;
        for (int d = 0; d < Dn; d++) a += rv2[h*Dn + d] * Wc[d*NC + c];
        w2c[t] = a;
    }
    __syncthreads();
    if (t < Bn*NC) {
        int b = t >> 1, c = t & 1;
        float p = 0.f;
        for (int h = 0; h < Hn; h++) p += g_acc1[b*Hn + h] * w2c[h*NC + c];
        out[t] = p * (1.0f/(float)Sn) + bc[c];
    }
    if (t == 256) out[256] = 0.f;
    if (t == 257) out[OUT_AE] = g_ae * (1.0f/(float)(Bn*Sn*Dn));
}

// ---------------- launch ----------------
extern "C" void kernel_launch(void* const* d_in, const int* in_sizes, int n_in,
                              void* d_out, int out_size) {
    const float* f   = (const float*)d_in[0];
    const float* tv  = (const float*)d_in[2];
    const float* rv1 = (const float*)d_in[3];
    const float* rv2 = (const float*)d_in[4];
    const float* Wc  = (const float*)d_in[5];
    const float* bc  = (const float*)d_in[6];
    float* out = (float*)d_out;

    static int attr_set = 0;
    if (!attr_set) {
        cudaFuncSetAttribute(k_topic, cudaFuncAttributeMaxDynamicSharedMemorySize,
                             T_TOT * (int)sizeof(float));
        cudaFuncSetAttribute(k_rec, cudaFuncAttributeMaxDynamicSharedMemorySize,
                             R_TOT * (int)sizeof(float));
        attr_set = 1;
    }

    k_init<<<128, 256>>>();
    k_prep<<<50, 256>>>(tv);
    k_far<<<1, 256>>>(out);

    k_topic<<<dim3(8, 128), 512, T_TOT * sizeof(float)>>>(f, out);

    k_topk_part<<<dim3(50, 4), 256>>>();
    k_topk_merge<<<1, 64>>>(out);

    k_rec<<<1024, 256, R_TOT * sizeof(float)>>>(rv1, rv2, out);

    k_final<<<1, 512>>>(rv2, Wc, bc, out);
}